// round 1
// baseline (speedup 1.0000x reference)
#include <cuda_runtime.h>
#include <cuda_bf16.h>

#define N_NODES  30000
#define N_EDGES  480000
#define N_GRAPHS 500
#define D1 78
#define D2 156
#define D3 312

// ---------------- scratch (device globals: no allocation allowed) ----------------
__device__ int   g_cnt[N_NODES];
__device__ int   g_cursor[N_NODES];
__device__ int   g_off[N_NODES + 1];
__device__ int   g_csr[N_EDGES];
__device__ float g_dinv[N_NODES];
__device__ float g_bufA[(size_t)N_NODES * D3];
__device__ float g_bufB[(size_t)N_NODES * D3];
__device__ float g_pooled[N_GRAPHS * D3];
__device__ float g_fc1[N_GRAPHS * 1024];

// ---------------- small utility kernels ----------------
__global__ void zero_int(int* p, int n) {
    int i = blockIdx.x * blockDim.x + threadIdx.x;
    if (i < n) p[i] = 0;
}

__global__ void count_deg(const int* __restrict__ dst, int* __restrict__ cnt, int E) {
    int e = blockIdx.x * blockDim.x + threadIdx.x;
    if (e < E) atomicAdd(&cnt[dst[e]], 1);
}

__global__ void compute_dinv(const int* __restrict__ cnt, float* __restrict__ dinv, int n) {
    int i = blockIdx.x * blockDim.x + threadIdx.x;
    if (i < n) dinv[i] = rsqrtf((float)cnt[i] + 1.0f);  // +1 self loop
}

// single-block exclusive scan: off[i] = sum_{j<i} cnt[j], off[n] = total
__global__ void scan_kernel(const int* __restrict__ cnt, int* __restrict__ off, int n) {
    const int T = 1024;
    int tid = threadIdx.x;
    int chunk = (n + T - 1) / T;
    int s = tid * chunk;
    int e = min(s + chunk, n);
    int sum = 0;
    for (int i = s; i < e; i++) sum += cnt[i];
    __shared__ int sm[T];
    sm[tid] = sum;
    __syncthreads();
    for (int d = 1; d < T; d <<= 1) {
        int t = (tid >= d) ? sm[tid - d] : 0;
        __syncthreads();
        sm[tid] += t;
        __syncthreads();
    }
    int run = sm[tid] - sum;  // exclusive prefix
    for (int i = s; i < e; i++) { off[i] = run; run += cnt[i]; }
    if (tid == T - 1) off[n] = run;
}

__global__ void scatter_edges(const int* __restrict__ src, const int* __restrict__ dst,
                              const int* __restrict__ off, int* __restrict__ cursor,
                              int* __restrict__ csr, int E) {
    int e = blockIdx.x * blockDim.x + threadIdx.x;
    if (e >= E) return;
    int d = dst[e];
    int pos = off[d] + atomicAdd(&cursor[d], 1);
    csr[pos] = src[e];
}

// ---------------- GCN aggregation in INPUT feature space ----------------
// a[i,:] = dinv[i] * sum_{e: dst=i} dinv[src_e] * x[src_e,:]  +  dinv[i]^2 * x[i,:]
// (then out = a @ W + b; linearity means this equals the reference's post-GEMM aggregation)
__global__ void aggregate_kernel(const float* __restrict__ x, const int* __restrict__ off,
                                 const int* __restrict__ csr, const float* __restrict__ dinv,
                                 float* __restrict__ out, int D) {
    int node = blockIdx.x;
    int f = threadIdx.x;
    int beg = off[node];
    int end = off[node + 1];
    float di = dinv[node];
    float acc = 0.f;
    if (f < D) acc = di * di * x[(size_t)node * D + f];
    for (int e = beg; e < end; e++) {
        int s = csr[e];
        float w = di * dinv[s];
        if (f < D) acc += w * x[(size_t)s * D + f];
    }
    if (f < D) out[(size_t)node * D + f] = acc;
}

// ---------------- fp32 tiled GEMM: C = A[MxK] @ B[KxN] + bias (optional relu) ----------------
template <bool RELU>
__global__ void gemm_bias(const float* __restrict__ A, const float* __restrict__ B,
                          const float* __restrict__ bias, float* __restrict__ C,
                          int M, int N, int K) {
    const int BM = 128, BN = 64, BK = 16, TM = 8, TN = 4;
    __shared__ float As[BK][BM];
    __shared__ float Bs[BK][BN];
    int tid = threadIdx.x;
    int tx = tid % 16;       // 16 col-groups of TN=4
    int ty = tid / 16;       // 16 row-groups of TM=8
    int row0 = blockIdx.y * BM;
    int col0 = blockIdx.x * BN;
    float acc[TM][TN] = {};
    for (int k0 = 0; k0 < K; k0 += BK) {
        for (int i = tid; i < BM * BK; i += 256) {
            int m = i / BK, kk = i % BK;
            float v = 0.f;
            if (row0 + m < M && k0 + kk < K) v = A[(size_t)(row0 + m) * K + k0 + kk];
            As[kk][m] = v;
        }
        for (int i = tid; i < BK * BN; i += 256) {
            int kk = i / BN, n = i % BN;
            float v = 0.f;
            if (k0 + kk < K && col0 + n < N) v = B[(size_t)(k0 + kk) * N + col0 + n];
            Bs[kk][n] = v;
        }
        __syncthreads();
#pragma unroll
        for (int kk = 0; kk < BK; kk++) {
            float a[TM], b[TN];
#pragma unroll
            for (int i = 0; i < TM; i++) a[i] = As[kk][ty * TM + i];
#pragma unroll
            for (int j = 0; j < TN; j++) b[j] = Bs[kk][tx * TN + j];
#pragma unroll
            for (int i = 0; i < TM; i++)
#pragma unroll
                for (int j = 0; j < TN; j++) acc[i][j] += a[i] * b[j];
        }
        __syncthreads();
    }
#pragma unroll
    for (int i = 0; i < TM; i++) {
        int m = row0 + ty * TM + i;
        if (m >= M) continue;
#pragma unroll
        for (int j = 0; j < TN; j++) {
            int n = col0 + tx * TN + j;
            if (n >= N) continue;
            float v = acc[i][j] + bias[n];
            if (RELU) v = fmaxf(v, 0.f);
            C[(size_t)m * N + n] = v;
        }
    }
}

// ---------------- global max pool (values are post-relu, >= 0 -> int atomicMax is valid) ----
__global__ void pool_max(const float* __restrict__ h, const int* __restrict__ batch,
                         int* __restrict__ pooled, int N, int D) {
    long idx = (long)blockIdx.x * blockDim.x + threadIdx.x;
    if (idx >= (long)N * D) return;
    int node = (int)(idx / D);
    int f = (int)(idx - (long)node * D);
    float v = h[idx];
    atomicMax(&pooled[batch[node] * D + f], __float_as_int(v));
}

// ---------------- launch ----------------
extern "C" void kernel_launch(void* const* d_in, const int* in_sizes, int n_in,
                              void* d_out, int out_size) {
    const float* x     = (const float*)d_in[0];
    const int*   ei    = (const int*)d_in[1];
    const int*   batch = (const int*)d_in[2];
    const float* W1 = (const float*)d_in[3];  const float* b1  = (const float*)d_in[4];
    const float* W2 = (const float*)d_in[5];  const float* b2  = (const float*)d_in[6];
    const float* W3 = (const float*)d_in[7];  const float* b3  = (const float*)d_in[8];
    const float* Wf1 = (const float*)d_in[9]; const float* bf1 = (const float*)d_in[10];
    const float* Wf2 = (const float*)d_in[11];const float* bf2 = (const float*)d_in[12];
    float* out = (float*)d_out;

    const int* src = ei;            // edge_index[0, :]
    const int* dst = ei + N_EDGES;  // edge_index[1, :]

    int *cnt, *cursor, *off, *csr;
    float *dinv, *bufA, *bufB, *pooled, *fc1;
    cudaGetSymbolAddress((void**)&cnt, g_cnt);
    cudaGetSymbolAddress((void**)&cursor, g_cursor);
    cudaGetSymbolAddress((void**)&off, g_off);
    cudaGetSymbolAddress((void**)&csr, g_csr);
    cudaGetSymbolAddress((void**)&dinv, g_dinv);
    cudaGetSymbolAddress((void**)&bufA, g_bufA);
    cudaGetSymbolAddress((void**)&bufB, g_bufB);
    cudaGetSymbolAddress((void**)&pooled, g_pooled);
    cudaGetSymbolAddress((void**)&fc1, g_fc1);

    const int TB = 256;
    // ---- CSR build (deterministic inputs; rebuilt every call) ----
    zero_int<<<(N_NODES + TB - 1) / TB, TB>>>(cnt, N_NODES);
    zero_int<<<(N_NODES + TB - 1) / TB, TB>>>(cursor, N_NODES);
    count_deg<<<(N_EDGES + TB - 1) / TB, TB>>>(dst, cnt, N_EDGES);
    compute_dinv<<<(N_NODES + TB - 1) / TB, TB>>>(cnt, dinv, N_NODES);
    scan_kernel<<<1, 1024>>>(cnt, off, N_NODES);
    scatter_edges<<<(N_EDGES + TB - 1) / TB, TB>>>(src, dst, off, cursor, csr, N_EDGES);

    // ---- layer 1: agg(x) @ W1 + b1, relu ----
    aggregate_kernel<<<N_NODES, 96>>>(x, off, csr, dinv, bufA, D1);
    gemm_bias<true><<<dim3((D1 + 63) / 64, (N_NODES + 127) / 128), 256>>>(
        bufA, W1, b1, bufB, N_NODES, D1, D1);

    // ---- layer 2: agg(h1) @ W2 + b2, relu ----
    aggregate_kernel<<<N_NODES, 96>>>(bufB, off, csr, dinv, bufA, D1);
    gemm_bias<true><<<dim3((D2 + 63) / 64, (N_NODES + 127) / 128), 256>>>(
        bufA, W2, b2, bufB, N_NODES, D2, D1);

    // ---- layer 3: agg(h2) @ W3 + b3, relu ----
    aggregate_kernel<<<N_NODES, 160>>>(bufB, off, csr, dinv, bufA, D2);
    gemm_bias<true><<<dim3((D3 + 63) / 64, (N_NODES + 127) / 128), 256>>>(
        bufA, W3, b3, bufB, N_NODES, D3, D2);

    // ---- global max pool over graphs ----
    zero_int<<<(N_GRAPHS * D3 + TB - 1) / TB, TB>>>((int*)pooled, N_GRAPHS * D3);
    {
        long total = (long)N_NODES * D3;
        pool_max<<<(int)((total + TB - 1) / TB), TB>>>(bufB, batch, (int*)pooled, N_NODES, D3);
    }

    // ---- FC head ----
    gemm_bias<true><<<dim3((1024 + 63) / 64, (N_GRAPHS + 127) / 128), 256>>>(
        pooled, Wf1, bf1, fc1, N_GRAPHS, 1024, D3);
    gemm_bias<false><<<dim3((128 + 63) / 64, (N_GRAPHS + 127) / 128), 256>>>(
        fc1, Wf2, bf2, out, N_GRAPHS, 128, 1024);
}

// round 2
// speedup vs baseline: 1.4371x; 1.4371x over previous
#include <cuda_runtime.h>
#include <cuda_bf16.h>
#include <cstdint>

#define N_NODES  30000
#define N_EDGES  480000
#define N_GRAPHS 500
#define D1 78
#define D2 156
#define D3 312

// ---------------- scratch (device globals: no allocation allowed) ----------------
__device__ int   g_cnt[N_NODES];
__device__ int   g_cursor[N_NODES];
__device__ int   g_off[N_NODES + 1];
__device__ int   g_csr[N_EDGES];
__device__ float g_dinv[N_NODES];
__device__ int   g_gstart[N_GRAPHS + 1];
__device__ float g_bufA[(size_t)N_NODES * D3];
__device__ float g_bufB[(size_t)N_NODES * D3];
__device__ float g_pooled[N_GRAPHS * D3];
__device__ float g_fc1[N_GRAPHS * 1024];

// ---------------- small utility kernels ----------------
__global__ void zero_int(int* p, int n) {
    int i = blockIdx.x * blockDim.x + threadIdx.x;
    if (i < n) p[i] = 0;
}

__global__ void count_deg(const int* __restrict__ dst, int* __restrict__ cnt, int E) {
    int e = blockIdx.x * blockDim.x + threadIdx.x;
    if (e < E) atomicAdd(&cnt[dst[e]], 1);
}

__global__ void compute_dinv(const int* __restrict__ cnt, float* __restrict__ dinv, int n) {
    int i = blockIdx.x * blockDim.x + threadIdx.x;
    if (i < n) dinv[i] = rsqrtf((float)cnt[i] + 1.0f);  // +1 self loop
}

// single-block exclusive scan: off[i] = sum_{j<i} cnt[j], off[n] = total
__global__ void scan_kernel(const int* __restrict__ cnt, int* __restrict__ off, int n) {
    const int T = 1024;
    int tid = threadIdx.x;
    int chunk = (n + T - 1) / T;
    int s = tid * chunk;
    int e = min(s + chunk, n);
    int sum = 0;
    for (int i = s; i < e; i++) sum += cnt[i];
    __shared__ int sm[T];
    sm[tid] = sum;
    __syncthreads();
    for (int d = 1; d < T; d <<= 1) {
        int t = (tid >= d) ? sm[tid - d] : 0;
        __syncthreads();
        sm[tid] += t;
        __syncthreads();
    }
    int run = sm[tid] - sum;  // exclusive prefix
    for (int i = s; i < e; i++) { off[i] = run; run += cnt[i]; }
    if (tid == T - 1) off[n] = run;
}

__global__ void scatter_edges(const int* __restrict__ src, const int* __restrict__ dst,
                              const int* __restrict__ off, int* __restrict__ cursor,
                              int* __restrict__ csr, int E) {
    int e = blockIdx.x * blockDim.x + threadIdx.x;
    if (e >= E) return;
    int d = dst[e];
    int pos = off[d] + atomicAdd(&cursor[d], 1);
    csr[pos] = src[e];
}

// ---------------- GCN aggregation in INPUT feature space ----------------
// a[i,:] = dinv[i] * sum_{e: dst=i} dinv[src_e] * x[src_e,:]  +  dinv[i]^2 * x[i,:]
__global__ void aggregate_kernel(const float* __restrict__ x, const int* __restrict__ off,
                                 const int* __restrict__ csr, const float* __restrict__ dinv,
                                 float* __restrict__ out, int D) {
    int node = blockIdx.x;
    int f = threadIdx.x;
    int beg = off[node];
    int end = off[node + 1];
    float di = dinv[node];
    float acc = 0.f;
    if (f < D) acc = di * di * x[(size_t)node * D + f];
    for (int e = beg; e < end; e++) {
        int s = csr[e];
        float w = di * dinv[s];
        if (f < D) acc += w * x[(size_t)s * D + f];
    }
    if (f < D) out[(size_t)node * D + f] = acc;
}

// ---------------- tf32 tensor-core GEMM (3-pass compensated, ~fp32 accuracy) --------
__device__ __forceinline__ uint32_t f2tf32(float x) {
    uint32_t r;
    asm("cvt.rna.tf32.f32 %0, %1;" : "=r"(r) : "f"(x));
    return r;
}

__device__ __forceinline__ void mma_tf32(float* c, const uint32_t* a, const uint32_t* b) {
    asm volatile(
        "mma.sync.aligned.m16n8k8.row.col.f32.tf32.tf32.f32 "
        "{%0,%1,%2,%3}, {%4,%5,%6,%7}, {%8,%9}, {%0,%1,%2,%3};\n"
        : "+f"(c[0]), "+f"(c[1]), "+f"(c[2]), "+f"(c[3])
        : "r"(a[0]), "r"(a[1]), "r"(a[2]), "r"(a[3]), "r"(b[0]), "r"(b[1]));
}

// C[M,N] = A[M,K] @ B[K,N] + bias, optional relu.  A,B,C row-major fp32.
// Block: 256 threads = 8 warps (2 warp-rows x 4 warp-cols). Tile: 128x64, BK=16.
template <bool RELU>
__global__ __launch_bounds__(256) void gemm_tf32(const float* __restrict__ A,
                                                 const float* __restrict__ B,
                                                 const float* __restrict__ bias,
                                                 float* __restrict__ C,
                                                 int M, int N, int K) {
    const int BM = 128, BN = 64, BK = 16;
    __shared__ float As[BK][BM + 8];   // stride 136 -> conflict-free fragment loads
    __shared__ float Bs[BK][BN + 8];   // stride 72  -> conflict-free fragment loads
    int tid = threadIdx.x;
    int warp = tid >> 5, lane = tid & 31;
    int g = lane >> 2, tig = lane & 3;
    int wm = warp >> 2, wn = warp & 3;            // 2 x 4 warp grid
    int row0 = blockIdx.y * BM, col0 = blockIdx.x * BN;

    float acc[4][2][4];
#pragma unroll
    for (int a = 0; a < 4; a++)
#pragma unroll
        for (int b = 0; b < 2; b++)
#pragma unroll
            for (int c = 0; c < 4; c++) acc[a][b][c] = 0.f;

    for (int k0 = 0; k0 < K; k0 += BK) {
        // A tile: 128x16, transposed store (zero-filled OOB)
#pragma unroll
        for (int j = 0; j < 8; j++) {
            int i = tid + j * 256;
            int m = i >> 4, k = i & 15;
            float v = 0.f;
            int gr = row0 + m, gk = k0 + k;
            if (gr < M && gk < K) v = A[(size_t)gr * K + gk];
            As[k][m] = v;
        }
        // B tile: 16x64
#pragma unroll
        for (int j = 0; j < 4; j++) {
            int i = tid + j * 256;
            int n = i & 63, k = i >> 6;
            float v = 0.f;
            int gn = col0 + n, gk = k0 + k;
            if (gk < K && gn < N) v = B[(size_t)gk * N + gn];
            Bs[k][n] = v;
        }
        __syncthreads();

#pragma unroll
        for (int ks = 0; ks < 2; ks++) {
            uint32_t bh[2][2], bl[2][2];
#pragma unroll
            for (int ni = 0; ni < 2; ni++) {
                int nc = wn * 16 + ni * 8 + g;
                float b0 = Bs[ks * 8 + tig][nc];
                float b1 = Bs[ks * 8 + tig + 4][nc];
                bh[ni][0] = f2tf32(b0);
                bl[ni][0] = f2tf32(b0 - __uint_as_float(bh[ni][0]));
                bh[ni][1] = f2tf32(b1);
                bl[ni][1] = f2tf32(b1 - __uint_as_float(bh[ni][1]));
            }
#pragma unroll
            for (int mi = 0; mi < 4; mi++) {
                int mr = wm * 64 + mi * 16 + g;
                float a0 = As[ks * 8 + tig][mr];
                float a1 = As[ks * 8 + tig][mr + 8];
                float a2 = As[ks * 8 + tig + 4][mr];
                float a3 = As[ks * 8 + tig + 4][mr + 8];
                uint32_t ah[4], al[4];
                ah[0] = f2tf32(a0); al[0] = f2tf32(a0 - __uint_as_float(ah[0]));
                ah[1] = f2tf32(a1); al[1] = f2tf32(a1 - __uint_as_float(ah[1]));
                ah[2] = f2tf32(a2); al[2] = f2tf32(a2 - __uint_as_float(ah[2]));
                ah[3] = f2tf32(a3); al[3] = f2tf32(a3 - __uint_as_float(ah[3]));
#pragma unroll
                for (int ni = 0; ni < 2; ni++) {
                    mma_tf32(acc[mi][ni], ah, bh[ni]);   // hi*hi
                    mma_tf32(acc[mi][ni], al, bh[ni]);   // lo*hi
                    mma_tf32(acc[mi][ni], ah, bl[ni]);   // hi*lo
                }
            }
        }
        __syncthreads();
    }

    // epilogue: bias + relu + store
#pragma unroll
    for (int mi = 0; mi < 4; mi++) {
        int r0 = row0 + wm * 64 + mi * 16 + g;
        int r1 = r0 + 8;
#pragma unroll
        for (int ni = 0; ni < 2; ni++) {
            int c0 = col0 + wn * 16 + ni * 8 + tig * 2;
            float bia0 = (c0 < N) ? bias[c0] : 0.f;
            float bia1 = (c0 + 1 < N) ? bias[c0 + 1] : 0.f;
            if (r0 < M) {
                if (c0 < N) {
                    float v = acc[mi][ni][0] + bia0;
                    if (RELU) v = fmaxf(v, 0.f);
                    C[(size_t)r0 * N + c0] = v;
                }
                if (c0 + 1 < N) {
                    float v = acc[mi][ni][1] + bia1;
                    if (RELU) v = fmaxf(v, 0.f);
                    C[(size_t)r0 * N + c0 + 1] = v;
                }
            }
            if (r1 < M) {
                if (c0 < N) {
                    float v = acc[mi][ni][2] + bia0;
                    if (RELU) v = fmaxf(v, 0.f);
                    C[(size_t)r1 * N + c0] = v;
                }
                if (c0 + 1 < N) {
                    float v = acc[mi][ni][3] + bia1;
                    if (RELU) v = fmaxf(v, 0.f);
                    C[(size_t)r1 * N + c0 + 1] = v;
                }
            }
        }
    }
}

// ---------------- pooling: batch is sorted -> segment bounds by binary search -------
__global__ void graph_bounds(const int* __restrict__ batch, int* __restrict__ gstart, int n) {
    int gidx = blockIdx.x * blockDim.x + threadIdx.x;
    if (gidx > N_GRAPHS) return;
    int lo = 0, hi = n;
    while (lo < hi) {
        int mid = (lo + hi) >> 1;
        if (batch[mid] < gidx) lo = mid + 1; else hi = mid;
    }
    gstart[gidx] = lo;
}

// block per graph; thread per feature; max over contiguous node rows (all >= 0 post-relu)
__global__ void pool_max_seg(const float* __restrict__ h, const int* __restrict__ gstart,
                             float* __restrict__ pooled) {
    int gr = blockIdx.x;
    int f = threadIdx.x;
    if (f >= D3) return;
    int beg = gstart[gr], end = gstart[gr + 1];
    float m = 0.f;  // empty segment -> 0 (matches isfinite guard; relu outputs >= 0)
    for (int node = beg; node < end; node++)
        m = fmaxf(m, h[(size_t)node * D3 + f]);
    pooled[gr * D3 + f] = m;
}

// ---------------- launch ----------------
extern "C" void kernel_launch(void* const* d_in, const int* in_sizes, int n_in,
                              void* d_out, int out_size) {
    const float* x     = (const float*)d_in[0];
    const int*   ei    = (const int*)d_in[1];
    const int*   batch = (const int*)d_in[2];
    const float* W1 = (const float*)d_in[3];  const float* b1  = (const float*)d_in[4];
    const float* W2 = (const float*)d_in[5];  const float* b2  = (const float*)d_in[6];
    const float* W3 = (const float*)d_in[7];  const float* b3  = (const float*)d_in[8];
    const float* Wf1 = (const float*)d_in[9]; const float* bf1 = (const float*)d_in[10];
    const float* Wf2 = (const float*)d_in[11];const float* bf2 = (const float*)d_in[12];
    float* out = (float*)d_out;

    const int* src = ei;            // edge_index[0, :]
    const int* dst = ei + N_EDGES;  // edge_index[1, :]

    int *cnt, *cursor, *off, *csr, *gstart;
    float *dinv, *bufA, *bufB, *pooled, *fc1;
    cudaGetSymbolAddress((void**)&cnt, g_cnt);
    cudaGetSymbolAddress((void**)&cursor, g_cursor);
    cudaGetSymbolAddress((void**)&off, g_off);
    cudaGetSymbolAddress((void**)&csr, g_csr);
    cudaGetSymbolAddress((void**)&gstart, g_gstart);
    cudaGetSymbolAddress((void**)&dinv, g_dinv);
    cudaGetSymbolAddress((void**)&bufA, g_bufA);
    cudaGetSymbolAddress((void**)&bufB, g_bufB);
    cudaGetSymbolAddress((void**)&pooled, g_pooled);
    cudaGetSymbolAddress((void**)&fc1, g_fc1);

    const int TB = 256;
    // ---- CSR build ----
    zero_int<<<(N_NODES + TB - 1) / TB, TB>>>(cnt, N_NODES);
    zero_int<<<(N_NODES + TB - 1) / TB, TB>>>(cursor, N_NODES);
    count_deg<<<(N_EDGES + TB - 1) / TB, TB>>>(dst, cnt, N_EDGES);
    compute_dinv<<<(N_NODES + TB - 1) / TB, TB>>>(cnt, dinv, N_NODES);
    scan_kernel<<<1, 1024>>>(cnt, off, N_NODES);
    scatter_edges<<<(N_EDGES + TB - 1) / TB, TB>>>(src, dst, off, cursor, csr, N_EDGES);

    // ---- layer 1: relu(agg(x) @ W1 + b1) ----
    aggregate_kernel<<<N_NODES, 96>>>(x, off, csr, dinv, bufA, D1);
    gemm_tf32<true><<<dim3((D1 + 63) / 64, (N_NODES + 127) / 128), 256>>>(
        bufA, W1, b1, bufB, N_NODES, D1, D1);

    // ---- layer 2 ----
    aggregate_kernel<<<N_NODES, 96>>>(bufB, off, csr, dinv, bufA, D1);
    gemm_tf32<true><<<dim3((D2 + 63) / 64, (N_NODES + 127) / 128), 256>>>(
        bufA, W2, b2, bufB, N_NODES, D2, D1);

    // ---- layer 3 ----
    aggregate_kernel<<<N_NODES, 160>>>(bufB, off, csr, dinv, bufA, D2);
    gemm_tf32<true><<<dim3((D3 + 63) / 64, (N_NODES + 127) / 128), 256>>>(
        bufA, W3, b3, bufB, N_NODES, D3, D2);

    // ---- global max pool (sorted batch -> segmented, atomic-free) ----
    graph_bounds<<<(N_GRAPHS + 1 + 127) / 128, 128>>>(batch, gstart, N_NODES);
    pool_max_seg<<<N_GRAPHS, 320>>>(bufB, gstart, pooled);

    // ---- FC head ----
    gemm_tf32<true><<<dim3((1024 + 63) / 64, (N_GRAPHS + 127) / 128), 256>>>(
        pooled, Wf1, bf1, fc1, N_GRAPHS, 1024, D3);
    gemm_tf32<false><<<dim3((128 + 63) / 64, (N_GRAPHS + 127) / 128), 256>>>(
        fc1, Wf2, bf2, out, N_GRAPHS, 128, 1024);
}

// round 3
// speedup vs baseline: 1.7219x; 1.1981x over previous
#include <cuda_runtime.h>
#include <cuda_bf16.h>
#include <cstdint>

#define N_NODES  30000
#define N_EDGES  480000
#define N_GRAPHS 500
#define D1 78
#define D2 156
#define D3 312

// ---------------- scratch (device globals: no allocation allowed) ----------------
__device__ int   g_cnt[N_NODES];
__device__ int   g_cursor[N_NODES];
__device__ int   g_off[N_NODES + 1];
__device__ int   g_csr[N_EDGES];
__device__ float g_dinv[N_NODES];
__device__ float g_bufA[(size_t)N_NODES * D3];
__device__ float g_bufB[(size_t)N_NODES * D3];
__device__ float g_pooled[N_GRAPHS * D3];
__device__ float g_fc1[N_GRAPHS * 1024];

// ---------------- CSR build ----------------
__global__ void zero_both(int4* cnt4, int4* cur4, int n4) {
    int i = blockIdx.x * blockDim.x + threadIdx.x;
    if (i < n4) {
        int4 z = make_int4(0, 0, 0, 0);
        cnt4[i] = z;
        cur4[i] = z;
    }
}

__global__ void count_deg(const int2* __restrict__ dst2, int* __restrict__ cnt, int e2) {
    int i = blockIdx.x * blockDim.x + threadIdx.x;
    if (i < e2) {
        int2 d = dst2[i];
        atomicAdd(&cnt[d.x], 1);
        atomicAdd(&cnt[d.y], 1);
    }
}

// single-block exclusive scan + dinv
__global__ void scan_dinv(const int* __restrict__ cnt, int* __restrict__ off,
                          float* __restrict__ dinv, int n) {
    const int T = 1024;
    int tid = threadIdx.x;
    int chunk = (n + T - 1) / T;
    int s = tid * chunk;
    int e = min(s + chunk, n);
    int sum = 0;
    for (int i = s; i < e; i++) {
        int c = cnt[i];
        dinv[i] = rsqrtf((float)c + 1.0f);
        sum += c;
    }
    __shared__ int sm[T];
    sm[tid] = sum;
    __syncthreads();
    for (int d = 1; d < T; d <<= 1) {
        int t = (tid >= d) ? sm[tid - d] : 0;
        __syncthreads();
        sm[tid] += t;
        __syncthreads();
    }
    int run = sm[tid] - sum;
    for (int i = s; i < e; i++) { off[i] = run; run += cnt[i]; }
    if (tid == T - 1) off[n] = run;
}

// scatter edges into CSR + pre-scale x by dinv (independent phases, one launch)
__global__ void scatter_scale(const int* __restrict__ src, const int* __restrict__ dst,
                              const int* __restrict__ off, int* __restrict__ cursor,
                              int* __restrict__ csr, const float* __restrict__ dinv,
                              const float2* __restrict__ x2, float2* __restrict__ y0) {
    int t = blockIdx.x * blockDim.x + threadIdx.x;
    if (t < N_EDGES) {
        int d = dst[t];
        int pos = off[d] + atomicAdd(&cursor[d], 1);
        csr[pos] = src[t];
    }
    const int DP = D1 / 2;  // 39
    int total = N_NODES * DP;
    int stride = gridDim.x * blockDim.x;
    for (int i = t; i < total; i += stride) {
        int node = i / DP;
        float2 v = x2[i];
        float di = dinv[node];
        y0[i] = make_float2(di * v.x, di * v.y);
    }
}

// ---------------- aggregation: a[i,:] = dinv[i] * (y[i,:] + sum_e y[src_e,:]) ------
// y rows are pre-scaled by dinv (y = dinv * h), so this equals sym-normalized GCN agg.
__global__ void aggregate_kernel(const float2* __restrict__ y, const int* __restrict__ off,
                                 const int* __restrict__ csr, const float* __restrict__ dinv,
                                 float2* __restrict__ out, int dp) {
    int node = blockIdx.x * blockDim.y + threadIdx.y;
    if (node >= N_NODES) return;
    int f = threadIdx.x;
    bool act = f < dp;
    int beg = off[node], end = off[node + 1];
    const float2* yb = y + f;
    float2 acc = act ? yb[(size_t)node * dp] : make_float2(0.f, 0.f);
    int e = beg;
    for (; e + 4 <= end; e += 4) {
        int s0 = csr[e], s1 = csr[e + 1], s2 = csr[e + 2], s3 = csr[e + 3];
        if (act) {
            float2 v0 = yb[(size_t)s0 * dp];
            float2 v1 = yb[(size_t)s1 * dp];
            float2 v2 = yb[(size_t)s2 * dp];
            float2 v3 = yb[(size_t)s3 * dp];
            acc.x += (v0.x + v1.x) + (v2.x + v3.x);
            acc.y += (v0.y + v1.y) + (v2.y + v3.y);
        }
    }
    for (; e < end; e++) {
        int s = csr[e];
        if (act) {
            float2 v = yb[(size_t)s * dp];
            acc.x += v.x; acc.y += v.y;
        }
    }
    if (act) {
        float di = dinv[node];
        out[(size_t)node * dp + f] = make_float2(di * acc.x, di * acc.y);
    }
}

// ---------------- tf32 tensor-core GEMM, 3-pass compensated, split done in SMEM ----
__device__ __forceinline__ uint32_t f2tf32(float x) {
    uint32_t r;
    asm("cvt.rna.tf32.f32 %0, %1;" : "=r"(r) : "f"(x));
    return r;
}

__device__ __forceinline__ void mma_tf32(float* c, const uint32_t* a, const uint32_t* b) {
    asm volatile(
        "mma.sync.aligned.m16n8k8.row.col.f32.tf32.tf32.f32 "
        "{%0,%1,%2,%3}, {%4,%5,%6,%7}, {%8,%9}, {%0,%1,%2,%3};\n"
        : "+f"(c[0]), "+f"(c[1]), "+f"(c[2]), "+f"(c[3])
        : "r"(a[0]), "r"(a[1]), "r"(a[2]), "r"(a[3]), "r"(b[0]), "r"(b[1]));
}

// C[M,N] = op(A[M,K] @ B[K,N] + bias); op = relu then optional per-row scale.
// Requires K, N even. 256 threads, 2x4 warp grid, tile 128x64, BK=16.
template <bool RELU, bool SCALE>
__global__ __launch_bounds__(256) void gemm_tf32(const float* __restrict__ A,
                                                 const float* __restrict__ B,
                                                 const float* __restrict__ bias,
                                                 const float* __restrict__ rowscale,
                                                 float* __restrict__ C,
                                                 int M, int N, int K) {
    const int BM = 128, BN = 64, BK = 16;
    __shared__ uint2 As[BK][BM + 4];   // stride 132 (8B units): frag reads conflict-free
    __shared__ uint2 Bs[BK][BN + 4];   // stride 68
    int tid = threadIdx.x;
    int warp = tid >> 5, lane = tid & 31;
    int g = lane >> 2, tig = lane & 3;
    int wm = warp >> 2, wn = warp & 3;
    int row0 = blockIdx.y * BM, col0 = blockIdx.x * BN;

    float acc[4][2][4];
#pragma unroll
    for (int a = 0; a < 4; a++)
#pragma unroll
        for (int b = 0; b < 2; b++)
#pragma unroll
            for (int c = 0; c < 4; c++) acc[a][b][c] = 0.f;

    for (int k0 = 0; k0 < K; k0 += BK) {
        // A tile 128x16 as 1024 float2, split hi/lo once here
#pragma unroll
        for (int j = 0; j < 4; j++) {
            int i = tid + j * 256;
            int m = i >> 3, c = i & 7;
            int gr = row0 + m, gk = k0 + 2 * c;
            float2 v = make_float2(0.f, 0.f);
            if (gr < M && gk < K) v = *reinterpret_cast<const float2*>(&A[(size_t)gr * K + gk]);
            uint32_t h0 = f2tf32(v.x), l0 = f2tf32(v.x - __uint_as_float(h0));
            uint32_t h1 = f2tf32(v.y), l1 = f2tf32(v.y - __uint_as_float(h1));
            As[2 * c][m]     = make_uint2(h0, l0);
            As[2 * c + 1][m] = make_uint2(h1, l1);
        }
        // B tile 16x64 as 512 float2
#pragma unroll
        for (int j = 0; j < 2; j++) {
            int i = tid + j * 256;
            int k = i >> 5, c = i & 31;
            int gk = k0 + k, gn = col0 + 2 * c;
            float2 v = make_float2(0.f, 0.f);
            if (gk < K && gn < N) v = *reinterpret_cast<const float2*>(&B[(size_t)gk * N + gn]);
            uint32_t h0 = f2tf32(v.x), l0 = f2tf32(v.x - __uint_as_float(h0));
            uint32_t h1 = f2tf32(v.y), l1 = f2tf32(v.y - __uint_as_float(h1));
            Bs[k][2 * c]     = make_uint2(h0, l0);
            Bs[k][2 * c + 1] = make_uint2(h1, l1);
        }
        __syncthreads();

#pragma unroll
        for (int ks = 0; ks < 2; ks++) {
            uint2 bf[2][2];
#pragma unroll
            for (int ni = 0; ni < 2; ni++) {
                int nc = wn * 16 + ni * 8 + g;
                bf[ni][0] = Bs[ks * 8 + tig][nc];
                bf[ni][1] = Bs[ks * 8 + tig + 4][nc];
            }
#pragma unroll
            for (int mi = 0; mi < 4; mi++) {
                int mr = wm * 64 + mi * 16 + g;
                uint2 a0 = As[ks * 8 + tig][mr];
                uint2 a1 = As[ks * 8 + tig][mr + 8];
                uint2 a2 = As[ks * 8 + tig + 4][mr];
                uint2 a3 = As[ks * 8 + tig + 4][mr + 8];
                uint32_t ah[4] = {a0.x, a1.x, a2.x, a3.x};
                uint32_t al[4] = {a0.y, a1.y, a2.y, a3.y};
#pragma unroll
                for (int ni = 0; ni < 2; ni++) {
                    uint32_t bh[2] = {bf[ni][0].x, bf[ni][1].x};
                    uint32_t bl[2] = {bf[ni][0].y, bf[ni][1].y};
                    mma_tf32(acc[mi][ni], ah, bh);
                    mma_tf32(acc[mi][ni], al, bh);
                    mma_tf32(acc[mi][ni], ah, bl);
                }
            }
        }
        __syncthreads();
    }

    // epilogue: bias (+relu) (+rowscale), float2 stores
#pragma unroll
    for (int mi = 0; mi < 4; mi++) {
        int r0 = row0 + wm * 64 + mi * 16 + g;
        int r1 = r0 + 8;
        float s0 = 1.f, s1 = 1.f;
        if (SCALE) {
            if (r0 < M) s0 = rowscale[r0];
            if (r1 < M) s1 = rowscale[r1];
        }
#pragma unroll
        for (int ni = 0; ni < 2; ni++) {
            int c0 = col0 + wn * 16 + ni * 8 + tig * 2;
            if (c0 < N) {
                float2 bia = *reinterpret_cast<const float2*>(&bias[c0]);
                if (r0 < M) {
                    float2 v = make_float2(acc[mi][ni][0] + bia.x, acc[mi][ni][1] + bia.y);
                    if (RELU) { v.x = fmaxf(v.x, 0.f); v.y = fmaxf(v.y, 0.f); }
                    if (SCALE) { v.x *= s0; v.y *= s0; }
                    *reinterpret_cast<float2*>(&C[(size_t)r0 * N + c0]) = v;
                }
                if (r1 < M) {
                    float2 v = make_float2(acc[mi][ni][2] + bia.x, acc[mi][ni][3] + bia.y);
                    if (RELU) { v.x = fmaxf(v.x, 0.f); v.y = fmaxf(v.y, 0.f); }
                    if (SCALE) { v.x *= s1; v.y *= s1; }
                    *reinterpret_cast<float2*>(&C[(size_t)r1 * N + c0]) = v;
                }
            }
        }
    }
}

// ---------------- max pool: fused bounds search + float4 strided max -----------------
__global__ void pool_kernel(const float4* __restrict__ h4, const int* __restrict__ batch,
                            float4* __restrict__ pooled4) {
    __shared__ int sb[2];
    __shared__ float4 red[4][80];
    int lane = threadIdx.x, ty = threadIdx.y, gr = blockIdx.x;
    if (ty == 0 && lane < 2) {
        int target = gr + lane, lo = 0, hi = N_NODES;
        while (lo < hi) { int mid = (lo + hi) >> 1; if (batch[mid] < target) lo = mid + 1; else hi = mid; }
        sb[lane] = lo;
    }
    __syncthreads();
    int beg = sb[0], end = sb[1];
    const int DQ = D3 / 4;  // 78
    float4 m = make_float4(0.f, 0.f, 0.f, 0.f);  // post-relu values >= 0; empty graph -> 0
    if (lane < DQ) {
        for (int node = beg + ty; node < end; node += 4) {
            float4 v = h4[(size_t)node * DQ + lane];
            m.x = fmaxf(m.x, v.x); m.y = fmaxf(m.y, v.y);
            m.z = fmaxf(m.z, v.z); m.w = fmaxf(m.w, v.w);
        }
    }
    red[ty][lane] = m;
    __syncthreads();
    if (ty == 0 && lane < DQ) {
        float4 a = red[0][lane], b = red[1][lane], c = red[2][lane], d = red[3][lane];
        float4 r;
        r.x = fmaxf(fmaxf(a.x, b.x), fmaxf(c.x, d.x));
        r.y = fmaxf(fmaxf(a.y, b.y), fmaxf(c.y, d.y));
        r.z = fmaxf(fmaxf(a.z, b.z), fmaxf(c.z, d.z));
        r.w = fmaxf(fmaxf(a.w, b.w), fmaxf(c.w, d.w));
        pooled4[(size_t)gr * DQ + lane] = r;
    }
}

// ---------------- launch ----------------
extern "C" void kernel_launch(void* const* d_in, const int* in_sizes, int n_in,
                              void* d_out, int out_size) {
    const float* x     = (const float*)d_in[0];
    const int*   ei    = (const int*)d_in[1];
    const int*   batch = (const int*)d_in[2];
    const float* W1 = (const float*)d_in[3];  const float* b1  = (const float*)d_in[4];
    const float* W2 = (const float*)d_in[5];  const float* b2  = (const float*)d_in[6];
    const float* W3 = (const float*)d_in[7];  const float* b3  = (const float*)d_in[8];
    const float* Wf1 = (const float*)d_in[9]; const float* bf1 = (const float*)d_in[10];
    const float* Wf2 = (const float*)d_in[11];const float* bf2 = (const float*)d_in[12];
    float* out = (float*)d_out;

    const int* src = ei;
    const int* dst = ei + N_EDGES;

    int *cnt, *cursor, *off, *csr;
    float *dinv, *bufA, *bufB, *pooled, *fc1;
    cudaGetSymbolAddress((void**)&cnt, g_cnt);
    cudaGetSymbolAddress((void**)&cursor, g_cursor);
    cudaGetSymbolAddress((void**)&off, g_off);
    cudaGetSymbolAddress((void**)&csr, g_csr);
    cudaGetSymbolAddress((void**)&dinv, g_dinv);
    cudaGetSymbolAddress((void**)&bufA, g_bufA);
    cudaGetSymbolAddress((void**)&bufB, g_bufB);
    cudaGetSymbolAddress((void**)&pooled, g_pooled);
    cudaGetSymbolAddress((void**)&fc1, g_fc1);

    // ---- CSR build + x pre-scale ----
    zero_both<<<(N_NODES / 4 + 255) / 256, 256>>>((int4*)cnt, (int4*)cursor, N_NODES / 4);
    count_deg<<<(N_EDGES / 2 + 255) / 256, 256>>>((const int2*)dst, cnt, N_EDGES / 2);
    scan_dinv<<<1, 1024>>>(cnt, off, dinv, N_NODES);
    scatter_scale<<<(N_EDGES + 255) / 256, 256>>>(src, dst, off, cursor, csr, dinv,
                                                  (const float2*)x, (float2*)bufA);

    // ---- layer 1: y1 = dinv * relu(agg(y0) @ W1 + b1) ----
    aggregate_kernel<<<(N_NODES + 5) / 6, dim3(40, 6)>>>((const float2*)bufA, off, csr, dinv,
                                                         (float2*)bufB, D1 / 2);
    gemm_tf32<true, true><<<dim3(2, (N_NODES + 127) / 128), 256>>>(
        bufB, W1, b1, dinv, bufA, N_NODES, D1, D1);

    // ---- layer 2: y2 = dinv * relu(agg(y1) @ W2 + b2) ----
    aggregate_kernel<<<(N_NODES + 5) / 6, dim3(40, 6)>>>((const float2*)bufA, off, csr, dinv,
                                                         (float2*)bufB, D1 / 2);
    gemm_tf32<true, true><<<dim3(3, (N_NODES + 127) / 128), 256>>>(
        bufB, W2, b2, dinv, bufA, N_NODES, D2, D1);

    // ---- layer 3: h3 = relu(agg(y2) @ W3 + b3) (unscaled, feeds pooling) ----
    aggregate_kernel<<<(N_NODES + 2) / 3, dim3(80, 3)>>>((const float2*)bufA, off, csr, dinv,
                                                         (float2*)bufB, D2 / 2);
    gemm_tf32<true, false><<<dim3(5, (N_NODES + 127) / 128), 256>>>(
        bufB, W3, b3, nullptr, bufA, N_NODES, D3, D2);

    // ---- global max pool ----
    pool_kernel<<<N_GRAPHS, dim3(80, 4)>>>((const float4*)bufA, batch, (float4*)pooled);

    // ---- FC head ----
    gemm_tf32<true, false><<<dim3(16, (N_GRAPHS + 127) / 128), 256>>>(
        pooled, Wf1, bf1, nullptr, fc1, N_GRAPHS, 1024, D3);
    gemm_tf32<false, false><<<dim3(2, (N_GRAPHS + 127) / 128), 256>>>(
        fc1, Wf2, bf2, nullptr, out, N_GRAPHS, 128, 1024);
}

// round 4
// speedup vs baseline: 2.4863x; 1.4440x over previous
#include <cuda_runtime.h>
#include <cuda_bf16.h>
#include <cstdint>

#define N_NODES  30000
#define N_EDGES  480000
#define N_GRAPHS 500
#define D1 78
#define D2 156
#define D3 312

// ---------------- scratch ----------------
__device__ int   g_cnt[N_NODES];
__device__ int   g_cursor[N_NODES];
__device__ int   g_off[N_NODES + 1];
__device__ int   g_csr[N_EDGES];
__device__ float g_dinv[N_NODES];
__device__ float g_y[(size_t)N_NODES * D3];          // f32 activations
__device__ uint2 g_s[(size_t)N_NODES * (D2 / 2)];    // split-bf16 packed GEMM input (max 78 pairs)
__device__ uint2 g_pooledS[N_GRAPHS * (D3 / 2)];
__device__ uint2 g_fc1S[N_GRAPHS * 512];
__device__ float g_h3_unused[1];
// weight fragments: uint4 per (chunk,ng,lane)
#define WF_OFF1 0
#define WF_OFF2 1600      // 5*10*32
#define WF_OFF3 4800      // +5*20*32
#define WF_OFFF1 17280    // +10*39*32
#define WF_OFFF2 99200    // +20*128*32
#define WF_TOTAL 131968   // +64*16*32
__device__ uint4 g_wfrag[WF_TOTAL];

// ---------------- bf16 split helpers ----------------
__device__ __forceinline__ uint32_t pack_bf16x2(float lo, float hi) {
    uint32_t r;
    asm("cvt.rn.bf16x2.f32 %0, %1, %2;" : "=r"(r) : "f"(hi), "f"(lo));
    return r;
}
// split float pair (x=even-k, y=odd-k) into (s0, s1) packed bf16x2 words
__device__ __forceinline__ uint2 split2(float x, float y) {
    uint32_t s0 = pack_bf16x2(x, y);
    float r0 = x - __uint_as_float(s0 << 16);
    float r1 = y - __uint_as_float(s0 & 0xffff0000u);
    uint32_t s1 = pack_bf16x2(r0, r1);
    return make_uint2(s0, s1);
}

__device__ __forceinline__ void mma_bf16(float* c, const uint32_t* a, const uint32_t* b) {
    asm volatile(
        "mma.sync.aligned.m16n8k16.row.col.f32.bf16.bf16.f32 "
        "{%0,%1,%2,%3}, {%4,%5,%6,%7}, {%8,%9}, {%0,%1,%2,%3};\n"
        : "+f"(c[0]), "+f"(c[1]), "+f"(c[2]), "+f"(c[3])
        : "r"(a[0]), "r"(a[1]), "r"(a[2]), "r"(a[3]), "r"(b[0]), "r"(b[1]));
}

// ---------------- CSR build ----------------
__global__ void zero_both(int4* cnt4, int4* cur4, int n4) {
    int i = blockIdx.x * blockDim.x + threadIdx.x;
    if (i < n4) {
        int4 z = make_int4(0, 0, 0, 0);
        cnt4[i] = z;
        cur4[i] = z;
    }
}

__global__ void count_deg(const int2* __restrict__ dst2, int* __restrict__ cnt, int e2) {
    int i = blockIdx.x * blockDim.x + threadIdx.x;
    if (i < e2) {
        int2 d = dst2[i];
        atomicAdd(&cnt[d.x], 1);
        atomicAdd(&cnt[d.y], 1);
    }
}

__global__ void scan_dinv(const int* __restrict__ cnt, int* __restrict__ off,
                          float* __restrict__ dinv, int n) {
    const int T = 1024;
    int tid = threadIdx.x;
    int chunk = (n + T - 1) / T;
    int s = tid * chunk;
    int e = min(s + chunk, n);
    int sum = 0;
    for (int i = s; i < e; i++) {
        int c = cnt[i];
        dinv[i] = rsqrtf((float)c + 1.0f);
        sum += c;
    }
    __shared__ int sm[T];
    sm[tid] = sum;
    __syncthreads();
    for (int d = 1; d < T; d <<= 1) {
        int t = (tid >= d) ? sm[tid - d] : 0;
        __syncthreads();
        sm[tid] += t;
        __syncthreads();
    }
    int run = sm[tid] - sum;
    for (int i = s; i < e; i++) { off[i] = run; run += cnt[i]; }
    if (tid == T - 1) off[n] = run;
}

// scatter edges into CSR + y0 = dinv * x (f32)
__global__ void scatter_scale(const int* __restrict__ src, const int* __restrict__ dst,
                              const int* __restrict__ off, int* __restrict__ cursor,
                              int* __restrict__ csr, const float* __restrict__ dinv,
                              const float2* __restrict__ x2, float2* __restrict__ y0) {
    int t = blockIdx.x * blockDim.x + threadIdx.x;
    if (t < N_EDGES) {
        int d = dst[t];
        int pos = off[d] + atomicAdd(&cursor[d], 1);
        csr[pos] = src[t];
    }
    const int DP = D1 / 2;
    int total = N_NODES * DP;
    int stride = gridDim.x * blockDim.x;
    for (int i = t; i < total; i += stride) {
        int node = i / DP;
        float2 v = x2[i];
        float di = dinv[node];
        y0[i] = make_float2(di * v.x, di * v.y);
    }
}

// ---------------- weight -> mma fragment conversion (once per launch) ----------------
// Fragment for m16n8k16 .row.col B: lane = ((n&7)<<2)|(p&3); uint4 = {s0r0,s0r1,s1r0,s1r1}
// r0 covers k = chunk*16 + 2*(lane&3) .. +1 ; r1 same + 8.
__global__ void conv_weights(const float* __restrict__ W, uint4* __restrict__ out,
                             int K, int N, int NG, int chunks) {
    int unit = blockIdx.x * 8 + (threadIdx.x >> 5);
    if (unit >= chunks * NG) return;
    int chunk = unit / NG, ng = unit % NG;
    int lane = threadIdx.x & 31;
    int n = ng * 8 + (lane >> 2);
    int k0 = chunk * 16 + 2 * (lane & 3);
    float f[4];
#pragma unroll
    for (int j = 0; j < 4; j++) {
        int k = k0 + (j >> 1) * 8 + (j & 1);
        f[j] = (k < K && n < N) ? W[(size_t)k * N + n] : 0.f;
    }
    uint2 p0 = split2(f[0], f[1]);
    uint2 p1 = split2(f[2], f[3]);
    out[(size_t)unit * 32 + lane] = make_uint4(p0.x, p1.x, p0.y, p1.y);
}

// ---------------- aggregation (reads f32 y, writes split-packed) ----------------
__global__ void aggregate_kernel(const float2* __restrict__ y, const int* __restrict__ off,
                                 const int* __restrict__ csr, const float* __restrict__ dinv,
                                 uint2* __restrict__ outS, int dp) {
    int node = blockIdx.x * blockDim.y + threadIdx.y;
    if (node >= N_NODES) return;
    int f = threadIdx.x;
    bool act = f < dp;
    int beg = off[node], end = off[node + 1];
    const float2* yb = y + f;
    float2 acc = act ? yb[(size_t)node * dp] : make_float2(0.f, 0.f);
    int e = beg;
    for (; e + 4 <= end; e += 4) {
        int s0 = csr[e], s1 = csr[e + 1], s2 = csr[e + 2], s3 = csr[e + 3];
        if (act) {
            float2 v0 = yb[(size_t)s0 * dp];
            float2 v1 = yb[(size_t)s1 * dp];
            float2 v2 = yb[(size_t)s2 * dp];
            float2 v3 = yb[(size_t)s3 * dp];
            acc.x += (v0.x + v1.x) + (v2.x + v3.x);
            acc.y += (v0.y + v1.y) + (v2.y + v3.y);
        }
    }
    for (; e < end; e++) {
        int s = csr[e];
        if (act) {
            float2 v = yb[(size_t)s * dp];
            acc.x += v.x; acc.y += v.y;
        }
    }
    if (act) {
        float di = dinv[node];
        outS[(size_t)node * dp + f] = split2(di * acc.x, di * acc.y);
    }
}

// ---------------- bf16-split tensor GEMM ----------------
// A: split-packed uint2 rows [M][KP] (KP = ceil(K/2)); B: pre-fragmented g_wfrag slice.
// C = op(A@B + bias). 256 thr, 2x4 warps, tile 128x64, k16 chunks.
template <bool RELU, bool SCALE, bool OSPLIT>
__global__ __launch_bounds__(256) void gemm_bf16s(const uint2* __restrict__ A, int KP,
                                                  const uint4* __restrict__ BF, int NG,
                                                  const float* __restrict__ bias,
                                                  const float* __restrict__ rowscale,
                                                  float* __restrict__ Cf,
                                                  uint2* __restrict__ Cs,
                                                  int M, int N, int K) {
    __shared__ uint4 ASf[2][8][32];
    uint32_t* ASw = reinterpret_cast<uint32_t*>(ASf);
    int tid = threadIdx.x;
    int warp = tid >> 5, lane = tid & 31;
    int g = lane >> 2, tig = lane & 3;
    int wm = warp >> 2, wn = warp & 3;
    int row0 = blockIdx.y * 128, col0 = blockIdx.x * 64;
    int chunks = (K + 15) >> 4;

    float acc[4][2][4];
#pragma unroll
    for (int a = 0; a < 4; a++)
#pragma unroll
        for (int b = 0; b < 2; b++)
#pragma unroll
            for (int c = 0; c < 4; c++) acc[a][b][c] = 0.f;

    int ngBase = (col0 >> 3) + wn * 2;

    for (int ch = 0; ch < chunks; ch++) {
        // B fragments straight from global (L1/L2 resident)
        uint4 bfr[2];
#pragma unroll
        for (int ni = 0; ni < 2; ni++) {
            int ng = ngBase + ni;
            bfr[ni] = (ng < NG) ? BF[((size_t)ch * NG + ng) * 32 + lane]
                                : make_uint4(0, 0, 0, 0);
        }
        // A loader: 1024 uint2 -> fragment layout
        int c0 = ch * 8;
#pragma unroll
        for (int j = 0; j < 4; j++) {
            int i = tid + j * 256;
            int m = i >> 3, c = i & 7;
            uint2 v = make_uint2(0, 0);
            int gr = row0 + m, gc = c0 + c;
            if (gr < M && gc < KP) v = A[(size_t)gr * KP + gc];
            int gi = m >> 4;
            int fl = ((m & 7) << 2) | (c & 3);
            int reg = ((m >> 3) & 1) | ((c >> 2) << 1);
            int w0 = ((gi * 32 + fl) << 2) + reg;
            ASw[w0] = v.x;
            ASw[w0 + 1024] = v.y;
        }
        __syncthreads();

#pragma unroll
        for (int mi = 0; mi < 4; mi++) {
            int gi = wm * 4 + mi;
            uint4 a0v = ASf[0][gi][lane];
            uint4 a1v = ASf[1][gi][lane];
            const uint32_t* a0 = reinterpret_cast<const uint32_t*>(&a0v);
            const uint32_t* a1 = reinterpret_cast<const uint32_t*>(&a1v);
#pragma unroll
            for (int ni = 0; ni < 2; ni++) {
                uint32_t b0[2] = {bfr[ni].x, bfr[ni].y};
                uint32_t b1[2] = {bfr[ni].z, bfr[ni].w};
                mma_bf16(acc[mi][ni], a0, b0);   // s0*s0
                mma_bf16(acc[mi][ni], a1, b0);   // s1*s0
                mma_bf16(acc[mi][ni], a0, b1);   // s0*s1
            }
        }
        __syncthreads();
    }

    // epilogue
#pragma unroll
    for (int mi = 0; mi < 4; mi++) {
        int r0 = row0 + wm * 64 + mi * 16 + g;
        int r1 = r0 + 8;
        float sc0 = 1.f, sc1 = 1.f;
        if (SCALE) {
            if (r0 < M) sc0 = rowscale[r0];
            if (r1 < M) sc1 = rowscale[r1];
        }
#pragma unroll
        for (int ni = 0; ni < 2; ni++) {
            int c0 = col0 + wn * 16 + ni * 8 + tig * 2;
            if (c0 < N) {
                float2 bia = *reinterpret_cast<const float2*>(&bias[c0]);
                if (r0 < M) {
                    float vx = acc[mi][ni][0] + bia.x, vy = acc[mi][ni][1] + bia.y;
                    if (RELU) { vx = fmaxf(vx, 0.f); vy = fmaxf(vy, 0.f); }
                    if (SCALE) { vx *= sc0; vy *= sc0; }
                    if (OSPLIT) Cs[(size_t)r0 * (N >> 1) + (c0 >> 1)] = split2(vx, vy);
                    else *reinterpret_cast<float2*>(&Cf[(size_t)r0 * N + c0]) = make_float2(vx, vy);
                }
                if (r1 < M) {
                    float vx = acc[mi][ni][2] + bia.x, vy = acc[mi][ni][3] + bia.y;
                    if (RELU) { vx = fmaxf(vx, 0.f); vy = fmaxf(vy, 0.f); }
                    if (SCALE) { vx *= sc1; vy *= sc1; }
                    if (OSPLIT) Cs[(size_t)r1 * (N >> 1) + (c0 >> 1)] = split2(vx, vy);
                    else *reinterpret_cast<float2*>(&Cf[(size_t)r1 * N + c0]) = make_float2(vx, vy);
                }
            }
        }
    }
}

// ---------------- max pool -> split-packed pooled ----------------
__global__ void pool_kernel(const float4* __restrict__ h4, const int* __restrict__ batch,
                            uint2* __restrict__ pooledS) {
    __shared__ int sb[2];
    __shared__ float4 red[4][80];
    int lane = threadIdx.x, ty = threadIdx.y, gr = blockIdx.x;
    if (ty == 0 && lane < 2) {
        int target = gr + lane, lo = 0, hi = N_NODES;
        while (lo < hi) { int mid = (lo + hi) >> 1; if (batch[mid] < target) lo = mid + 1; else hi = mid; }
        sb[lane] = lo;
    }
    __syncthreads();
    int beg = sb[0], end = sb[1];
    const int DQ = D3 / 4;  // 78
    float4 m = make_float4(0.f, 0.f, 0.f, 0.f);
    if (lane < DQ) {
        for (int node = beg + ty; node < end; node += 4) {
            float4 v = h4[(size_t)node * DQ + lane];
            m.x = fmaxf(m.x, v.x); m.y = fmaxf(m.y, v.y);
            m.z = fmaxf(m.z, v.z); m.w = fmaxf(m.w, v.w);
        }
    }
    red[ty][lane] = m;
    __syncthreads();
    if (ty == 0 && lane < DQ) {
        float4 a = red[0][lane], b = red[1][lane], c = red[2][lane], d = red[3][lane];
        float4 r;
        r.x = fmaxf(fmaxf(a.x, b.x), fmaxf(c.x, d.x));
        r.y = fmaxf(fmaxf(a.y, b.y), fmaxf(c.y, d.y));
        r.z = fmaxf(fmaxf(a.z, b.z), fmaxf(c.z, d.z));
        r.w = fmaxf(fmaxf(a.w, b.w), fmaxf(c.w, d.w));
        pooledS[(size_t)gr * (D3 / 2) + 2 * lane]     = split2(r.x, r.y);
        pooledS[(size_t)gr * (D3 / 2) + 2 * lane + 1] = split2(r.z, r.w);
    }
}

// ---------------- launch ----------------
extern "C" void kernel_launch(void* const* d_in, const int* in_sizes, int n_in,
                              void* d_out, int out_size) {
    const float* x     = (const float*)d_in[0];
    const int*   ei    = (const int*)d_in[1];
    const int*   batch = (const int*)d_in[2];
    const float* W1 = (const float*)d_in[3];  const float* b1  = (const float*)d_in[4];
    const float* W2 = (const float*)d_in[5];  const float* b2  = (const float*)d_in[6];
    const float* W3 = (const float*)d_in[7];  const float* b3  = (const float*)d_in[8];
    const float* Wf1 = (const float*)d_in[9]; const float* bf1 = (const float*)d_in[10];
    const float* Wf2 = (const float*)d_in[11];const float* bf2 = (const float*)d_in[12];
    float* out = (float*)d_out;

    const int* src = ei;
    const int* dst = ei + N_EDGES;

    int *cnt, *cursor, *off, *csr;
    float *dinv, *y;
    uint2 *s, *pooledS, *fc1S;
    uint4 *wf;
    cudaGetSymbolAddress((void**)&cnt, g_cnt);
    cudaGetSymbolAddress((void**)&cursor, g_cursor);
    cudaGetSymbolAddress((void**)&off, g_off);
    cudaGetSymbolAddress((void**)&csr, g_csr);
    cudaGetSymbolAddress((void**)&dinv, g_dinv);
    cudaGetSymbolAddress((void**)&y, g_y);
    cudaGetSymbolAddress((void**)&s, g_s);
    cudaGetSymbolAddress((void**)&pooledS, g_pooledS);
    cudaGetSymbolAddress((void**)&fc1S, g_fc1S);
    cudaGetSymbolAddress((void**)&wf, g_wfrag);

    // ---- weight fragment conversion (5 tiny launches) ----
    conv_weights<<<(5 * 10 + 7) / 8, 256>>>(W1, wf + WF_OFF1, D1, D1, 10, 5);
    conv_weights<<<(5 * 20 + 7) / 8, 256>>>(W2, wf + WF_OFF2, D1, D2, 20, 5);
    conv_weights<<<(10 * 39 + 7) / 8, 256>>>(W3, wf + WF_OFF3, D2, D3, 39, 10);
    conv_weights<<<(20 * 128 + 7) / 8, 256>>>(Wf1, wf + WF_OFFF1, D3, 1024, 128, 20);
    conv_weights<<<(64 * 16 + 7) / 8, 256>>>(Wf2, wf + WF_OFFF2, 1024, 128, 16, 64);

    // ---- CSR build + y0 = dinv*x ----
    zero_both<<<(N_NODES / 4 + 255) / 256, 256>>>((int4*)cnt, (int4*)cursor, N_NODES / 4);
    count_deg<<<(N_EDGES / 2 + 255) / 256, 256>>>((const int2*)dst, cnt, N_EDGES / 2);
    scan_dinv<<<1, 1024>>>(cnt, off, dinv, N_NODES);
    scatter_scale<<<(N_EDGES + 255) / 256, 256>>>(src, dst, off, cursor, csr, dinv,
                                                  (const float2*)x, (float2*)y);

    // ---- layer 1 ----
    aggregate_kernel<<<(N_NODES + 5) / 6, dim3(40, 6)>>>((const float2*)y, off, csr, dinv,
                                                         s, D1 / 2);
    gemm_bf16s<true, true, false><<<dim3(2, (N_NODES + 127) / 128), 256>>>(
        s, D1 / 2, wf + WF_OFF1, 10, b1, dinv, y, nullptr, N_NODES, D1, D1);

    // ---- layer 2 ----
    aggregate_kernel<<<(N_NODES + 5) / 6, dim3(40, 6)>>>((const float2*)y, off, csr, dinv,
                                                         s, D1 / 2);
    gemm_bf16s<true, true, false><<<dim3(3, (N_NODES + 127) / 128), 256>>>(
        s, D1 / 2, wf + WF_OFF2, 20, b2, dinv, y, nullptr, N_NODES, D2, D1);

    // ---- layer 3 (unscaled output feeds pooling) ----
    aggregate_kernel<<<(N_NODES + 2) / 3, dim3(80, 3)>>>((const float2*)y, off, csr, dinv,
                                                         s, D2 / 2);
    gemm_bf16s<true, false, false><<<dim3(5, (N_NODES + 127) / 128), 256>>>(
        s, D2 / 2, wf + WF_OFF3, 39, b3, nullptr, y, nullptr, N_NODES, D3, D2);

    // ---- pool ----
    pool_kernel<<<N_GRAPHS, dim3(80, 4)>>>((const float4*)y, batch, pooledS);

    // ---- FC head ----
    gemm_bf16s<true, false, true><<<dim3(16, (N_GRAPHS + 127) / 128), 256>>>(
        pooledS, D3 / 2, wf + WF_OFFF1, 128, bf1, nullptr, nullptr, fc1S, N_GRAPHS, 1024, D3);
    gemm_bf16s<false, false, false><<<dim3(2, (N_GRAPHS + 127) / 128), 256>>>(
        fc1S, 512, wf + WF_OFFF2, 16, bf2, nullptr, out, nullptr, N_GRAPHS, 128, 1024);
}